// round 1
// baseline (speedup 1.0000x reference)
#include <cuda_runtime.h>

#define BATCH 2
#define SEQ   2048
#define EMB   128
#define NH    8
#define HD    16
#define NROWS (BATCH*SEQ)
#define KT    128

// Scratch for head-split Q/K/V in [b][h][s][d] layout (d contiguous, 64B rows).
__device__ float g_Q[BATCH*NH*SEQ*HD];
__device__ float g_K[BATCH*NH*SEQ*HD];
__device__ float g_V[BATCH*NH*SEQ*HD];

typedef unsigned long long u64;

__device__ __forceinline__ u64 pack2(float lo, float hi){
    u64 r; asm("mov.b64 %0, {%1, %2};" : "=l"(r) : "f"(lo), "f"(hi)); return r;
}
__device__ __forceinline__ void unpack2(u64 v, float& a, float& b){
    asm("mov.b64 {%0, %1}, %2;" : "=f"(a), "=f"(b) : "l"(v));
}
__device__ __forceinline__ u64 fma2(u64 a, u64 b, u64 c){
    u64 d; asm("fma.rn.f32x2 %0, %1, %2, %3;" : "=l"(d) : "l"(a), "l"(b), "l"(c)); return d;
}
__device__ __forceinline__ u64 mul2(u64 a, u64 b){
    u64 d; asm("mul.rn.f32x2 %0, %1, %2;" : "=l"(d) : "l"(a), "l"(b)); return d;
}
__device__ __forceinline__ float ex2f(float x){
    float y; asm("ex2.approx.ftz.f32 %0, %1;" : "=f"(y) : "f"(x)); return y;
}

// ---------------------------------------------------------------------------
// Kernel 1: fused QKV projection + head split.
// out col c of X@W maps to head h = c&7, dim d = c>>3 (reshape(B,S,hd,H)).
// Grid: NROWS/32 CTAs, 256 threads. Each thread: 4 rows x 4 cols x 3 mats.
// ---------------------------------------------------------------------------
__global__ __launch_bounds__(256) void qkv_kernel(
    const float* __restrict__ X,
    const float* __restrict__ Wq, const float* __restrict__ Wk,
    const float* __restrict__ Wv)
{
    __shared__ __align__(16) float Xs[32][EMB];
    const int r0 = blockIdx.x * 32;
    {
        const float4* xg = (const float4*)(X + (size_t)r0 * EMB);
        float4* xs = (float4*)&Xs[0][0];
        #pragma unroll
        for (int i = 0; i < 4; i++)
            xs[threadIdx.x + 256 * i] = xg[threadIdx.x + 256 * i];
    }
    __syncthreads();

    const int oc = threadIdx.x & 31;
    const int c4 = oc * 4;
    const int rg = threadIdx.x >> 5;   // 0..7 -> rows rg*4 .. rg*4+3

    float aq[4][4], ak[4][4], av[4][4];
    #pragma unroll
    for (int i = 0; i < 4; i++)
        #pragma unroll
        for (int j = 0; j < 4; j++) { aq[i][j] = 0.f; ak[i][j] = 0.f; av[i][j] = 0.f; }

    for (int e0 = 0; e0 < EMB; e0 += 4) {
        float4 xr[4];
        #pragma unroll
        for (int i = 0; i < 4; i++)
            xr[i] = *(const float4*)&Xs[rg * 4 + i][e0];
        #pragma unroll
        for (int ee = 0; ee < 4; ee++) {
            const int e = e0 + ee;
            float4 wq = *(const float4*)(Wq + e * EMB + c4);
            float4 wk = *(const float4*)(Wk + e * EMB + c4);
            float4 wv = *(const float4*)(Wv + e * EMB + c4);
            #pragma unroll
            for (int i = 0; i < 4; i++) {
                float x = (ee == 0) ? xr[i].x : (ee == 1) ? xr[i].y
                        : (ee == 2) ? xr[i].z : xr[i].w;
                aq[i][0] += x * wq.x; aq[i][1] += x * wq.y;
                aq[i][2] += x * wq.z; aq[i][3] += x * wq.w;
                ak[i][0] += x * wk.x; ak[i][1] += x * wk.y;
                ak[i][2] += x * wk.z; ak[i][3] += x * wk.w;
                av[i][0] += x * wv.x; av[i][1] += x * wv.y;
                av[i][2] += x * wv.z; av[i][3] += x * wv.w;
            }
        }
    }

    #pragma unroll
    for (int i = 0; i < 4; i++) {
        const int r = r0 + rg * 4 + i;
        const int b = r >> 11;            // r / SEQ
        const int s = r & (SEQ - 1);      // r % SEQ
        #pragma unroll
        for (int j = 0; j < 4; j++) {
            const int c = c4 + j;
            const int h = c & 7;
            const int d = c >> 3;
            const int idx = (((b * NH + h) * SEQ + s) * HD) + d;
            g_Q[idx] = aq[i][j];
            g_K[idx] = ak[i][j];
            g_V[idx] = av[i][j];
        }
    }
}

// ---------------------------------------------------------------------------
// Kernel 2: flash attention. Grid (SEQ/128, BATCH*NH), 128 threads.
// One thread per query row; K/V streamed through SMEM in KT=128 tiles.
// Softmax in log2 domain: log2(e)/sqrt(hd) folded into q; mask adds
// -1000*log2(e). Online rescale per 16-key chunk.
// ---------------------------------------------------------------------------
__global__ __launch_bounds__(128) void attn_kernel(
    const int* __restrict__ mask_src, float* __restrict__ out)
{
    __shared__ __align__(16) float Ks[KT * HD];
    __shared__ __align__(16) float Vs[KT * HD];
    __shared__ float addm[KT];

    const int bh = blockIdx.y;
    const int b  = bh >> 3;
    const int h  = bh & 7;
    const int q  = blockIdx.x * 128 + threadIdx.x;

    const float* Qb = g_Q + (size_t)bh * SEQ * HD;
    const float* Kb = g_K + (size_t)bh * SEQ * HD;
    const float* Vb = g_V + (size_t)bh * SEQ * HD;

    // q scaled by log2(e)/sqrt(HD)
    u64 q2[8];
    {
        const float SC = 0.3606737602222409f;  // 1.4426950408889634 / 4
        const float4* qp = (const float4*)(Qb + q * HD);
        #pragma unroll
        for (int i = 0; i < 4; i++) {
            float4 v = qp[i];
            q2[2 * i]     = pack2(v.x * SC, v.y * SC);
            q2[2 * i + 1] = pack2(v.z * SC, v.w * SC);
        }
    }

    float m = -1e30f, l = 0.f;
    u64 acc[8];
    #pragma unroll
    for (int i = 0; i < 8; i++) acc[i] = pack2(0.f, 0.f);

    const float NEGM = -1442.6950408889634f;  // -1000 * log2(e)

    for (int kb = 0; kb < SEQ; kb += KT) {
        __syncthreads();
        {
            const float4* kg = (const float4*)(Kb + kb * HD);
            const float4* vg = (const float4*)(Vb + kb * HD);
            float4* ks = (float4*)Ks;
            float4* vs = (float4*)Vs;
            #pragma unroll
            for (int i = 0; i < 4; i++) {
                const int idx = threadIdx.x + 128 * i;
                ks[idx] = kg[idx];
                vs[idx] = vg[idx];
            }
            addm[threadIdx.x] = mask_src[b * SEQ + kb + threadIdx.x] ? 0.f : NEGM;
        }
        __syncthreads();

        #pragma unroll 1
        for (int c = 0; c < KT; c += 16) {
            float s[16];
            float cm = -1e30f;
            #pragma unroll
            for (int kk = 0; kk < 16; kk++) {
                const double2* kr = (const double2*)(Ks + (c + kk) * HD);
                double2 p0 = kr[0], p1 = kr[1], p2 = kr[2], p3 = kr[3];
                u64 t = mul2(q2[0], __double_as_longlong(p0.x));
                t = fma2(q2[1], __double_as_longlong(p0.y), t);
                t = fma2(q2[2], __double_as_longlong(p1.x), t);
                t = fma2(q2[3], __double_as_longlong(p1.y), t);
                t = fma2(q2[4], __double_as_longlong(p2.x), t);
                t = fma2(q2[5], __double_as_longlong(p2.y), t);
                t = fma2(q2[6], __double_as_longlong(p3.x), t);
                t = fma2(q2[7], __double_as_longlong(p3.y), t);
                float ta, tb; unpack2(t, ta, tb);
                const float sv = ta + tb + addm[c + kk];
                s[kk] = sv;
                cm = fmaxf(cm, sv);
            }
            const float newm = fmaxf(m, cm);
            const float corr = ex2f(m - newm);
            l *= corr;
            const u64 c2 = pack2(corr, corr);
            #pragma unroll
            for (int i = 0; i < 8; i++) acc[i] = mul2(acc[i], c2);
            m = newm;

            #pragma unroll
            for (int kk = 0; kk < 16; kk++) {
                const float p = ex2f(s[kk] - m);
                l += p;
                const u64 pp = pack2(p, p);
                const double2* vr = (const double2*)(Vs + (c + kk) * HD);
                double2 v0 = vr[0], v1 = vr[1], v2 = vr[2], v3 = vr[3];
                acc[0] = fma2(pp, __double_as_longlong(v0.x), acc[0]);
                acc[1] = fma2(pp, __double_as_longlong(v0.y), acc[1]);
                acc[2] = fma2(pp, __double_as_longlong(v1.x), acc[2]);
                acc[3] = fma2(pp, __double_as_longlong(v1.y), acc[3]);
                acc[4] = fma2(pp, __double_as_longlong(v2.x), acc[4]);
                acc[5] = fma2(pp, __double_as_longlong(v2.y), acc[5]);
                acc[6] = fma2(pp, __double_as_longlong(v3.x), acc[6]);
                acc[7] = fma2(pp, __double_as_longlong(v3.y), acc[7]);
            }
        }
    }

    // out[b][s][d*NH + h] = acc[d] / l   (inverse head split)
    const float invl = 1.f / l;
    float* op = out + ((size_t)(b * SEQ + q)) * EMB + h;
    #pragma unroll
    for (int j = 0; j < 8; j++) {
        float a, bb; unpack2(acc[j], a, bb);
        op[(2 * j) * NH]     = a  * invl;
        op[(2 * j + 1) * NH] = bb * invl;
    }
}

extern "C" void kernel_launch(void* const* d_in, const int* in_sizes, int n_in,
                              void* d_out, int out_size)
{
    const float* X    = (const float*)d_in[0];
    const int*   msk  = (const int*)d_in[1];
    // d_in[2] = target mask (unused in encoder path), d_in[3] = masked flag (0)
    const float* Wq   = (const float*)d_in[4];
    const float* Wk   = (const float*)d_in[5];
    const float* Wv   = (const float*)d_in[6];
    float* out        = (float*)d_out;

    qkv_kernel<<<NROWS / 32, 256>>>(X, Wq, Wk, Wv);

    dim3 grid(SEQ / 128, BATCH * NH);
    attn_kernel<<<grid, 128>>>(msk, out);
}

// round 2
// speedup vs baseline: 1.0286x; 1.0286x over previous
#include <cuda_runtime.h>

#define BATCH 2
#define SEQ   2048
#define EMB   128
#define NH    8
#define HD    16
#define NROWS (BATCH*SEQ)
#define KT    128        // keys per smem tile
#define KROW  20         // padded floats per K/V smem row (80B, conflict-free for 4-way split)
#define QPC   64         // queries per CTA
#define NSPL  4          // KV splits per query (lanes l, l^8, l^16, l^24)

// Scratch for head-split Q/K/V in [b][h][s][d] layout (d contiguous, 64B rows).
__device__ float g_Q[BATCH*NH*SEQ*HD];
__device__ float g_K[BATCH*NH*SEQ*HD];
__device__ float g_V[BATCH*NH*SEQ*HD];

typedef unsigned long long u64;

__device__ __forceinline__ u64 pack2(float lo, float hi){
    u64 r; asm("mov.b64 %0, {%1, %2};" : "=l"(r) : "f"(lo), "f"(hi)); return r;
}
__device__ __forceinline__ void unpack2(u64 v, float& a, float& b){
    asm("mov.b64 {%0, %1}, %2;" : "=f"(a), "=f"(b) : "l"(v));
}
__device__ __forceinline__ u64 fma2(u64 a, u64 b, u64 c){
    u64 d; asm("fma.rn.f32x2 %0, %1, %2, %3;" : "=l"(d) : "l"(a), "l"(b), "l"(c)); return d;
}
__device__ __forceinline__ u64 mul2(u64 a, u64 b){
    u64 d; asm("mul.rn.f32x2 %0, %1, %2;" : "=l"(d) : "l"(a), "l"(b)); return d;
}
__device__ __forceinline__ float ex2f(float x){
    float y; asm("ex2.approx.ftz.f32 %0, %1;" : "=f"(y) : "f"(x)); return y;
}

// ---------------------------------------------------------------------------
// Kernel 1: fused QKV projection + head split (unchanged from R1 — 14us).
// ---------------------------------------------------------------------------
__global__ __launch_bounds__(256) void qkv_kernel(
    const float* __restrict__ X,
    const float* __restrict__ Wq, const float* __restrict__ Wk,
    const float* __restrict__ Wv)
{
    __shared__ __align__(16) float Xs[32][EMB];
    const int r0 = blockIdx.x * 32;
    {
        const float4* xg = (const float4*)(X + (size_t)r0 * EMB);
        float4* xs = (float4*)&Xs[0][0];
        #pragma unroll
        for (int i = 0; i < 4; i++)
            xs[threadIdx.x + 256 * i] = xg[threadIdx.x + 256 * i];
    }
    __syncthreads();

    const int oc = threadIdx.x & 31;
    const int c4 = oc * 4;
    const int rg = threadIdx.x >> 5;

    float aq[4][4], ak[4][4], av[4][4];
    #pragma unroll
    for (int i = 0; i < 4; i++)
        #pragma unroll
        for (int j = 0; j < 4; j++) { aq[i][j] = 0.f; ak[i][j] = 0.f; av[i][j] = 0.f; }

    for (int e0 = 0; e0 < EMB; e0 += 4) {
        float4 xr[4];
        #pragma unroll
        for (int i = 0; i < 4; i++)
            xr[i] = *(const float4*)&Xs[rg * 4 + i][e0];
        #pragma unroll
        for (int ee = 0; ee < 4; ee++) {
            const int e = e0 + ee;
            float4 wq = *(const float4*)(Wq + e * EMB + c4);
            float4 wk = *(const float4*)(Wk + e * EMB + c4);
            float4 wv = *(const float4*)(Wv + e * EMB + c4);
            #pragma unroll
            for (int i = 0; i < 4; i++) {
                float x = (ee == 0) ? xr[i].x : (ee == 1) ? xr[i].y
                        : (ee == 2) ? xr[i].z : xr[i].w;
                aq[i][0] += x * wq.x; aq[i][1] += x * wq.y;
                aq[i][2] += x * wq.z; aq[i][3] += x * wq.w;
                ak[i][0] += x * wk.x; ak[i][1] += x * wk.y;
                ak[i][2] += x * wk.z; ak[i][3] += x * wk.w;
                av[i][0] += x * wv.x; av[i][1] += x * wv.y;
                av[i][2] += x * wv.z; av[i][3] += x * wv.w;
            }
        }
    }

    #pragma unroll
    for (int i = 0; i < 4; i++) {
        const int r = r0 + rg * 4 + i;
        const int b = r >> 11;
        const int s = r & (SEQ - 1);
        #pragma unroll
        for (int j = 0; j < 4; j++) {
            const int c = c4 + j;
            const int h = c & 7;
            const int d = c >> 3;
            const int idx = (((b * NH + h) * SEQ + s) * HD) + d;
            g_Q[idx] = aq[i][j];
            g_K[idx] = ak[i][j];
            g_V[idx] = av[i][j];
        }
    }
}

// ---------------------------------------------------------------------------
// Kernel 2: flash attention, 4-way KV split per query.
// Grid (SEQ/QPC=32, BATCH*NH=16), 256 threads (8 warps).
// Warp w, lane l: query = blockIdx.x*QPC + w*8 + (l&7), split = l>>3.
// Split s processes keys (4*jj + s) of each 128-key tile.
// Partials merged via 2 butterfly shfl rounds at the end.
// ---------------------------------------------------------------------------
__global__ __launch_bounds__(256, 3) void attn_kernel(
    const int* __restrict__ mask_src, float* __restrict__ out)
{
    __shared__ __align__(16) float Ks[KT * KROW];
    __shared__ __align__(16) float Vs[KT * KROW];
    __shared__ float addm[KT];

    const int tid  = threadIdx.x;
    const int w    = tid >> 5;
    const int lane = tid & 31;
    const int spl  = lane >> 3;          // 0..3
    const int bh = blockIdx.y;
    const int b  = bh >> 3;
    const int h  = bh & 7;
    const int q  = blockIdx.x * QPC + w * 8 + (lane & 7);

    const float* Qb = g_Q + (size_t)bh * SEQ * HD;
    const float* Kb = g_K + (size_t)bh * SEQ * HD;
    const float* Vb = g_V + (size_t)bh * SEQ * HD;

    // q scaled by log2(e)/sqrt(HD)
    u64 q2[8];
    {
        const float SC = 0.3606737602222409f;  // 1.4426950408889634 / 4
        const float4* qp = (const float4*)(Qb + q * HD);
        #pragma unroll
        for (int i = 0; i < 4; i++) {
            float4 v = qp[i];
            q2[2 * i]     = pack2(v.x * SC, v.y * SC);
            q2[2 * i + 1] = pack2(v.z * SC, v.w * SC);
        }
    }

    float m = -1e30f, l = 0.f;
    u64 acc[8];
    #pragma unroll
    for (int i = 0; i < 8; i++) acc[i] = pack2(0.f, 0.f);

    const float NEGM = -1442.6950408889634f;  // -1000 * log2(e)

    for (int kb = 0; kb < SEQ; kb += KT) {
        __syncthreads();
        {
            // Fill K/V tiles into padded smem rows (KROW floats per row).
            const float4* kg = (const float4*)(Kb + kb * HD);
            const float4* vg = (const float4*)(Vb + kb * HD);
            #pragma unroll
            for (int i = 0; i < 2; i++) {
                const int idx = tid + 256 * i;      // float4 index, 512 total
                const int row = idx >> 2;
                const int c4  = (idx & 3) * 4;
                *(float4*)&Ks[row * KROW + c4] = kg[idx];
                *(float4*)&Vs[row * KROW + c4] = vg[idx];
            }
            if (tid < KT)
                addm[tid] = mask_src[b * SEQ + kb + tid] ? 0.f : NEGM;
        }
        __syncthreads();

        // This split's keys: local index 4*jj + spl, jj in [0,32)
        #pragma unroll
        for (int c = 0; c < 32; c += 16) {
            float s[16];
            float cm = -1e30f;
            #pragma unroll
            for (int kk = 0; kk < 16; kk++) {
                const int krow = ((c + kk) << 2) + spl;
                const double2* kr = (const double2*)(Ks + krow * KROW);
                double2 p0 = kr[0], p1 = kr[1], p2 = kr[2], p3 = kr[3];
                u64 t = mul2(q2[0], __double_as_longlong(p0.x));
                t = fma2(q2[1], __double_as_longlong(p0.y), t);
                t = fma2(q2[2], __double_as_longlong(p1.x), t);
                t = fma2(q2[3], __double_as_longlong(p1.y), t);
                t = fma2(q2[4], __double_as_longlong(p2.x), t);
                t = fma2(q2[5], __double_as_longlong(p2.y), t);
                t = fma2(q2[6], __double_as_longlong(p3.x), t);
                t = fma2(q2[7], __double_as_longlong(p3.y), t);
                float ta, tb; unpack2(t, ta, tb);
                const float sv = ta + tb + addm[krow];
                s[kk] = sv;
                cm = fmaxf(cm, sv);
            }
            const float newm = fmaxf(m, cm);
            const float corr = ex2f(m - newm);
            l *= corr;
            const u64 c2 = pack2(corr, corr);
            #pragma unroll
            for (int i = 0; i < 8; i++) acc[i] = mul2(acc[i], c2);
            m = newm;

            #pragma unroll
            for (int kk = 0; kk < 16; kk++) {
                const float p = ex2f(s[kk] - m);
                l += p;
                const u64 pp = pack2(p, p);
                const int krow = ((c + kk) << 2) + spl;
                const double2* vr = (const double2*)(Vs + krow * KROW);
                double2 v0 = vr[0], v1 = vr[1], v2 = vr[2], v3 = vr[3];
                acc[0] = fma2(pp, __double_as_longlong(v0.x), acc[0]);
                acc[1] = fma2(pp, __double_as_longlong(v0.y), acc[1]);
                acc[2] = fma2(pp, __double_as_longlong(v1.x), acc[2]);
                acc[3] = fma2(pp, __double_as_longlong(v1.y), acc[3]);
                acc[4] = fma2(pp, __double_as_longlong(v2.x), acc[4]);
                acc[5] = fma2(pp, __double_as_longlong(v2.y), acc[5]);
                acc[6] = fma2(pp, __double_as_longlong(v3.x), acc[6]);
                acc[7] = fma2(pp, __double_as_longlong(v3.y), acc[7]);
            }
        }
    }

    // Combine the 4 split partials (lanes l, l^8, l^16 hold same query).
    float accf[16];
    #pragma unroll
    for (int i = 0; i < 8; i++) unpack2(acc[i], accf[2 * i], accf[2 * i + 1]);

    #pragma unroll
    for (int off = 8; off <= 16; off <<= 1) {
        const float mo = __shfl_xor_sync(0xFFFFFFFFu, m, off);
        const float M  = fmaxf(m, mo);
        const float c  = ex2f(m - M);
        m = M;
        l *= c;
        l += __shfl_xor_sync(0xFFFFFFFFu, l, off);
        #pragma unroll
        for (int i = 0; i < 16; i++) {
            accf[i] *= c;
            accf[i] += __shfl_xor_sync(0xFFFFFFFFu, accf[i], off);
        }
    }

    if (spl == 0) {
        // out[b][s][d*NH + h] = accf[d] / l   (inverse head split)
        const float invl = 1.f / l;
        float* op = out + ((size_t)(b * SEQ + q)) * EMB + h;
        #pragma unroll
        for (int j = 0; j < 16; j++)
            op[j * NH] = accf[j] * invl;
    }
}

extern "C" void kernel_launch(void* const* d_in, const int* in_sizes, int n_in,
                              void* d_out, int out_size)
{
    const float* X    = (const float*)d_in[0];
    const int*   msk  = (const int*)d_in[1];
    // d_in[2] = target mask (unused, encoder path), d_in[3] = masked flag (0)
    const float* Wq   = (const float*)d_in[4];
    const float* Wk   = (const float*)d_in[5];
    const float* Wv   = (const float*)d_in[6];
    float* out        = (float*)d_out;

    qkv_kernel<<<NROWS / 32, 256>>>(X, Wq, Wk, Wv);

    dim3 grid(SEQ / QPC, BATCH * NH);
    attn_kernel<<<grid, 256>>>(msk, out);
}

// round 3
// speedup vs baseline: 1.2950x; 1.2590x over previous
#include <cuda_runtime.h>

#define BATCH 2
#define SEQ   2048
#define EMB   128
#define NH    8
#define HD    16
#define NROWS (BATCH*SEQ)
#define KT    128        // keys per smem tile
#define KROW  20         // padded floats per K/V smem row (80B, conflict-free 4-way split)

// Scratch for head-split Q/K/V in [b][h][s][d] layout (d contiguous, 64B rows).
__device__ float g_Q[BATCH*NH*SEQ*HD];
__device__ float g_K[BATCH*NH*SEQ*HD];
__device__ float g_V[BATCH*NH*SEQ*HD];

typedef unsigned long long u64;

__device__ __forceinline__ u64 pack2(float lo, float hi){
    u64 r; asm("mov.b64 %0, {%1, %2};" : "=l"(r) : "f"(lo), "f"(hi)); return r;
}
__device__ __forceinline__ void unpack2(u64 v, float& a, float& b){
    asm("mov.b64 {%0, %1}, %2;" : "=f"(a), "=f"(b) : "l"(v));
}
__device__ __forceinline__ u64 fma2(u64 a, u64 b, u64 c){
    u64 d; asm("fma.rn.f32x2 %0, %1, %2, %3;" : "=l"(d) : "l"(a), "l"(b), "l"(c)); return d;
}
__device__ __forceinline__ u64 mul2(u64 a, u64 b){
    u64 d; asm("mul.rn.f32x2 %0, %1, %2;" : "=l"(d) : "l"(a), "l"(b)); return d;
}
__device__ __forceinline__ float ex2f(float x){
    float y; asm("ex2.approx.ftz.f32 %0, %1;" : "=f"(y) : "f"(x)); return y;
}

// ---------------------------------------------------------------------------
// Kernel 1: fused QKV projection + head split (unchanged).
// ---------------------------------------------------------------------------
__global__ __launch_bounds__(256) void qkv_kernel(
    const float* __restrict__ X,
    const float* __restrict__ Wq, const float* __restrict__ Wk,
    const float* __restrict__ Wv)
{
    __shared__ __align__(16) float Xs[32][EMB];
    const int r0 = blockIdx.x * 32;
    {
        const float4* xg = (const float4*)(X + (size_t)r0 * EMB);
        float4* xs = (float4*)&Xs[0][0];
        #pragma unroll
        for (int i = 0; i < 4; i++)
            xs[threadIdx.x + 256 * i] = xg[threadIdx.x + 256 * i];
    }
    __syncthreads();

    const int oc = threadIdx.x & 31;
    const int c4 = oc * 4;
    const int rg = threadIdx.x >> 5;

    float aq[4][4], ak[4][4], av[4][4];
    #pragma unroll
    for (int i = 0; i < 4; i++)
        #pragma unroll
        for (int j = 0; j < 4; j++) { aq[i][j] = 0.f; ak[i][j] = 0.f; av[i][j] = 0.f; }

    for (int e0 = 0; e0 < EMB; e0 += 4) {
        float4 xr[4];
        #pragma unroll
        for (int i = 0; i < 4; i++)
            xr[i] = *(const float4*)&Xs[rg * 4 + i][e0];
        #pragma unroll
        for (int ee = 0; ee < 4; ee++) {
            const int e = e0 + ee;
            float4 wq = *(const float4*)(Wq + e * EMB + c4);
            float4 wk = *(const float4*)(Wk + e * EMB + c4);
            float4 wv = *(const float4*)(Wv + e * EMB + c4);
            #pragma unroll
            for (int i = 0; i < 4; i++) {
                float x = (ee == 0) ? xr[i].x : (ee == 1) ? xr[i].y
                        : (ee == 2) ? xr[i].z : xr[i].w;
                aq[i][0] += x * wq.x; aq[i][1] += x * wq.y;
                aq[i][2] += x * wq.z; aq[i][3] += x * wq.w;
                ak[i][0] += x * wk.x; ak[i][1] += x * wk.y;
                ak[i][2] += x * wk.z; ak[i][3] += x * wk.w;
                av[i][0] += x * wv.x; av[i][1] += x * wv.y;
                av[i][2] += x * wv.z; av[i][3] += x * wv.w;
            }
        }
    }

    #pragma unroll
    for (int i = 0; i < 4; i++) {
        const int r = r0 + rg * 4 + i;
        const int b = r >> 11;
        const int s = r & (SEQ - 1);
        #pragma unroll
        for (int j = 0; j < 4; j++) {
            const int c = c4 + j;
            const int h = c & 7;
            const int d = c >> 3;
            const int idx = (((b * NH + h) * SEQ + s) * HD) + d;
            g_Q[idx] = aq[i][j];
            g_K[idx] = ak[i][j];
            g_V[idx] = av[i][j];
        }
    }
}

// ---------------------------------------------------------------------------
// Kernel 2: flash attention, 2 queries per thread, 4-way KV split.
// Grid (SEQ/64, BATCH*NH), 128 threads (4 warps).
// Warp w, lane l: queries 2*(l&7), 2*(l&7)+1 of group; split = l>>3 processes
// keys (4*j + spl). Each K/V row load serves both queries (halves LDS/query).
// Partials merged via 2 butterfly shfl rounds (offsets 8, 16).
// ---------------------------------------------------------------------------
__global__ __launch_bounds__(128, 4) void attn_kernel(
    const int* __restrict__ mask_src, float* __restrict__ out)
{
    __shared__ __align__(16) float Ks[KT * KROW];
    __shared__ __align__(16) float Vs[KT * KROW];
    __shared__ float addm[KT];

    const int tid  = threadIdx.x;
    const int w    = tid >> 5;
    const int lane = tid & 31;
    const int spl  = lane >> 3;          // 0..3
    const int bh = blockIdx.y;
    const int b  = bh >> 3;
    const int h  = bh & 7;
    const int qA = blockIdx.x * 64 + w * 16 + (lane & 7) * 2;
    const int qB = qA + 1;

    const float* Qb = g_Q + (size_t)bh * SEQ * HD;
    const float* Kb = g_K + (size_t)bh * SEQ * HD;
    const float* Vb = g_V + (size_t)bh * SEQ * HD;

    // q scaled by log2(e)/sqrt(HD)
    u64 qa2[8], qb2[8];
    {
        const float SC = 0.3606737602222409f;  // 1.4426950408889634 / 4
        const float4* pa = (const float4*)(Qb + qA * HD);
        const float4* pb = (const float4*)(Qb + qB * HD);
        #pragma unroll
        for (int i = 0; i < 4; i++) {
            float4 va = pa[i], vb = pb[i];
            qa2[2*i]   = pack2(va.x * SC, va.y * SC);
            qa2[2*i+1] = pack2(va.z * SC, va.w * SC);
            qb2[2*i]   = pack2(vb.x * SC, vb.y * SC);
            qb2[2*i+1] = pack2(vb.z * SC, vb.w * SC);
        }
    }

    float mA = -1e30f, lA = 0.f, mB = -1e30f, lB = 0.f;
    u64 accA[8], accB[8];
    #pragma unroll
    for (int i = 0; i < 8; i++) { accA[i] = pack2(0.f, 0.f); accB[i] = pack2(0.f, 0.f); }

    const float NEGM = -1442.6950408889634f;  // -1000 * log2(e)

    for (int kb = 0; kb < SEQ; kb += KT) {
        __syncthreads();
        {
            const float4* kg = (const float4*)(Kb + kb * HD);
            const float4* vg = (const float4*)(Vb + kb * HD);
            #pragma unroll
            for (int i = 0; i < 4; i++) {
                const int idx = tid + 128 * i;      // float4 index, 512 total
                const int row = idx >> 2;
                const int c4  = (idx & 3) * 4;
                *(float4*)&Ks[row * KROW + c4] = kg[idx];
                *(float4*)&Vs[row * KROW + c4] = vg[idx];
            }
            addm[tid] = mask_src[b * SEQ + kb + tid] ? 0.f : NEGM;
        }
        __syncthreads();

        // This split's keys: local index 4*j + spl, j in [0,32), chunks of 8.
        #pragma unroll
        for (int c = 0; c < 32; c += 8) {
            float sA[8], sB[8];
            float cmA = -1e30f, cmB = -1e30f;
            #pragma unroll
            for (int kk = 0; kk < 8; kk++) {
                const int krow = ((c + kk) << 2) + spl;
                const double2* kr = (const double2*)(Ks + krow * KROW);
                double2 p0 = kr[0], p1 = kr[1], p2 = kr[2], p3 = kr[3];
                const u64 k0 = __double_as_longlong(p0.x), k1 = __double_as_longlong(p0.y);
                const u64 k2 = __double_as_longlong(p1.x), k3 = __double_as_longlong(p1.y);
                const u64 k4 = __double_as_longlong(p2.x), k5 = __double_as_longlong(p2.y);
                const u64 k6 = __double_as_longlong(p3.x), k7 = __double_as_longlong(p3.y);
                u64 tA = mul2(qa2[0], k0);
                u64 tB = mul2(qb2[0], k0);
                tA = fma2(qa2[1], k1, tA);  tB = fma2(qb2[1], k1, tB);
                tA = fma2(qa2[2], k2, tA);  tB = fma2(qb2[2], k2, tB);
                tA = fma2(qa2[3], k3, tA);  tB = fma2(qb2[3], k3, tB);
                tA = fma2(qa2[4], k4, tA);  tB = fma2(qb2[4], k4, tB);
                tA = fma2(qa2[5], k5, tA);  tB = fma2(qb2[5], k5, tB);
                tA = fma2(qa2[6], k6, tA);  tB = fma2(qb2[6], k6, tB);
                tA = fma2(qa2[7], k7, tA);  tB = fma2(qb2[7], k7, tB);
                const float am = addm[krow];
                float ta0, ta1, tb0, tb1;
                unpack2(tA, ta0, ta1);
                unpack2(tB, tb0, tb1);
                const float svA = ta0 + ta1 + am;
                const float svB = tb0 + tb1 + am;
                sA[kk] = svA;  cmA = fmaxf(cmA, svA);
                sB[kk] = svB;  cmB = fmaxf(cmB, svB);
            }
            {
                const float nmA = fmaxf(mA, cmA);
                const float coA = ex2f(mA - nmA);
                lA *= coA;  mA = nmA;
                const u64 cA2 = pack2(coA, coA);
                const float nmB = fmaxf(mB, cmB);
                const float coB = ex2f(mB - nmB);
                lB *= coB;  mB = nmB;
                const u64 cB2 = pack2(coB, coB);
                #pragma unroll
                for (int i = 0; i < 8; i++) {
                    accA[i] = mul2(accA[i], cA2);
                    accB[i] = mul2(accB[i], cB2);
                }
            }
            #pragma unroll
            for (int kk = 0; kk < 8; kk++) {
                const float pA = ex2f(sA[kk] - mA);
                const float pB = ex2f(sB[kk] - mB);
                lA += pA;  lB += pB;
                const u64 ppA = pack2(pA, pA);
                const u64 ppB = pack2(pB, pB);
                const int krow = ((c + kk) << 2) + spl;
                const double2* vr = (const double2*)(Vs + krow * KROW);
                double2 v0 = vr[0], v1 = vr[1], v2 = vr[2], v3 = vr[3];
                const u64 w0 = __double_as_longlong(v0.x), w1 = __double_as_longlong(v0.y);
                const u64 w2 = __double_as_longlong(v1.x), w3 = __double_as_longlong(v1.y);
                const u64 w4 = __double_as_longlong(v2.x), w5 = __double_as_longlong(v2.y);
                const u64 w6 = __double_as_longlong(v3.x), w7 = __double_as_longlong(v3.y);
                accA[0] = fma2(ppA, w0, accA[0]);  accB[0] = fma2(ppB, w0, accB[0]);
                accA[1] = fma2(ppA, w1, accA[1]);  accB[1] = fma2(ppB, w1, accB[1]);
                accA[2] = fma2(ppA, w2, accA[2]);  accB[2] = fma2(ppB, w2, accB[2]);
                accA[3] = fma2(ppA, w3, accA[3]);  accB[3] = fma2(ppB, w3, accB[3]);
                accA[4] = fma2(ppA, w4, accA[4]);  accB[4] = fma2(ppB, w4, accB[4]);
                accA[5] = fma2(ppA, w5, accA[5]);  accB[5] = fma2(ppB, w5, accB[5]);
                accA[6] = fma2(ppA, w6, accA[6]);  accB[6] = fma2(ppB, w6, accB[6]);
                accA[7] = fma2(ppA, w7, accA[7]);  accB[7] = fma2(ppB, w7, accB[7]);
            }
        }
    }

    // Combine the 4 split partials (lanes l, l^8, l^16 hold same query pair).
    float fA[16], fB[16];
    #pragma unroll
    for (int i = 0; i < 8; i++) {
        unpack2(accA[i], fA[2*i], fA[2*i+1]);
        unpack2(accB[i], fB[2*i], fB[2*i+1]);
    }

    #pragma unroll
    for (int off = 8; off <= 16; off <<= 1) {
        {
            const float mo = __shfl_xor_sync(0xFFFFFFFFu, mA, off);
            const float M  = fmaxf(mA, mo);
            const float c  = ex2f(mA - M);
            mA = M;  lA *= c;
            lA += __shfl_xor_sync(0xFFFFFFFFu, lA, off);
            #pragma unroll
            for (int i = 0; i < 16; i++) {
                fA[i] *= c;
                fA[i] += __shfl_xor_sync(0xFFFFFFFFu, fA[i], off);
            }
        }
        {
            const float mo = __shfl_xor_sync(0xFFFFFFFFu, mB, off);
            const float M  = fmaxf(mB, mo);
            const float c  = ex2f(mB - M);
            mB = M;  lB *= c;
            lB += __shfl_xor_sync(0xFFFFFFFFu, lB, off);
            #pragma unroll
            for (int i = 0; i < 16; i++) {
                fB[i] *= c;
                fB[i] += __shfl_xor_sync(0xFFFFFFFFu, fB[i], off);
            }
        }
    }

    if (spl == 0) {
        // out[b][s][d*NH + h] = f[d] / l   (inverse head split)
        const float iA = 1.f / lA;
        const float iB = 1.f / lB;
        float* opA = out + ((size_t)(b * SEQ + qA)) * EMB + h;
        float* opB = out + ((size_t)(b * SEQ + qB)) * EMB + h;
        #pragma unroll
        for (int j = 0; j < 16; j++) {
            opA[j * NH] = fA[j] * iA;
            opB[j * NH] = fB[j] * iB;
        }
    }
}

extern "C" void kernel_launch(void* const* d_in, const int* in_sizes, int n_in,
                              void* d_out, int out_size)
{
    const float* X    = (const float*)d_in[0];
    const int*   msk  = (const int*)d_in[1];
    // d_in[2] = target mask (unused, encoder path), d_in[3] = masked flag (0)
    const float* Wq   = (const float*)d_in[4];
    const float* Wk   = (const float*)d_in[5];
    const float* Wv   = (const float*)d_in[6];
    float* out        = (float*)d_out;

    qkv_kernel<<<NROWS / 32, 256>>>(X, Wq, Wk, Wv);

    dim3 grid(SEQ / 64, BATCH * NH);
    attn_kernel<<<grid, 128>>>(msk, out);
}